// round 14
// baseline (speedup 1.0000x reference)
#include <cuda_runtime.h>
#include <math.h>

#define NB 2
#define NV 1300
#define NF 2500
#define IH 128
#define IW 128
#define EPSV 1e-8f
#define NSPLIT 32
#define CHMAX 80    // ceil(2500/32)=79, rounded
#define TAU 1e-4f

// Scratch (allocation-free rule: __device__ globals; zero-initialized at load)
__device__ float g_vtx[NB][NV][3];              // ndcx, ndcy, viewz (for shade)
__device__ float g_vn[NB][NV][3];               // accumulated vertex normals (zeroed by shade tail)
// inverted keys: 0 = empty. key = ~((depthbits<<32)|face). atomicMax == min over (depth,face).
__device__ unsigned long long g_best[NB][IH * IW];
__device__ int g_donecnt;                       // shade-block completion counter

__device__ __noinline__ float3 xform(float x, float y, float z) {
    float vz = 2.0f - z;                 // view = verts @ diag(-1,1,-1) + (0,0,2)
    float nx = 12.0f * (-x) / vz;
    float ny = 12.0f * y / vz;
    return make_float3(nx, ny, vz);
}

// Single fused front kernel:
//  z-slice NSPLIT : vertex transform (g_vtx) + vertex-normal atomics (g_vn)
//  z-slices 0..31 : raster — 32x32 pixel tile per block, 2x2 pixels per thread,
//                   face records computed IN-BLOCK (R13-proven bit-identical)
__global__ void __launch_bounds__(256) k_render(const float* __restrict__ verts,
                                                const int* __restrict__ faces) {
    int tid = threadIdx.x;

    if (blockIdx.z == NSPLIT) {
        int idx = (blockIdx.y * gridDim.x + blockIdx.x) * 256 + tid;
        if (idx < NB * NV) {
            int b = idx / NV, v = idx - b * NV;
            float3 t = xform(verts[idx * 3 + 0], verts[idx * 3 + 1], verts[idx * 3 + 2]);
            g_vtx[b][v][0] = t.x;
            g_vtx[b][v][1] = t.y;
            g_vtx[b][v][2] = t.z;
        }
        if (idx < NB * NF) {
            int b = idx / NF, f = idx - b * NF;
            int i0 = faces[f * 3 + 0];
            int i1 = faces[f * 3 + 1];
            int i2 = faces[f * 3 + 2];
            const float* w0 = &verts[(b * NV + i0) * 3];
            const float* w1 = &verts[(b * NV + i1) * 3];
            const float* w2 = &verts[(b * NV + i2) * 3];
            float ax = w1[0] - w0[0], ay = w1[1] - w0[1], az = w1[2] - w0[2];
            float bx = w2[0] - w0[0], by = w2[1] - w0[1], bz = w2[2] - w0[2];
            float fx = ay * bz - az * by;
            float fy = az * bx - ax * bz;
            float fz = ax * by - ay * bx;
            atomicAdd(&g_vn[b][i0][0], fx); atomicAdd(&g_vn[b][i0][1], fy); atomicAdd(&g_vn[b][i0][2], fz);
            atomicAdd(&g_vn[b][i1][0], fx); atomicAdd(&g_vn[b][i1][1], fy); atomicAdd(&g_vn[b][i1][2], fz);
            atomicAdd(&g_vn[b][i2][0], fx); atomicAdd(&g_vn[b][i2][1], fy); atomicAdd(&g_vn[b][i2][2], fz);
        }
        return;
    }

    __shared__ float4 sm[CHMAX * 3];
    __shared__ unsigned sbb[CHMAX];
    __shared__ unsigned cbb[CHMAX];          // compacted bbox words (list order)
    __shared__ unsigned short cidx[CHMAX];   // compacted face indices (ascending)
    __shared__ int warpcnt[8];
    __shared__ int warpoff[8];
    __shared__ int nlist;

    int b = blockIdx.y;
    int chunk = blockIdx.z;
    int warp = tid >> 5, lane = tid & 31;
    // 32x32 tile: 4x4 tiles per image
    int jx0 = (blockIdx.x & 3) << 5;
    int iy0 = (blockIdx.x >> 2) << 5;
    // 2x2 pixel quad per thread (16x16 quads)
    int j0 = jx0 + ((tid & 15) << 1);
    int i0q = iy0 + ((tid >> 4) << 1);
    float pxq[2], pyq[2];
    pxq[0] = 1.0f - (2.0f * (float)j0 + 1.0f) * (1.0f / (float)IW);
    pxq[1] = 1.0f - (2.0f * (float)(j0 + 1) + 1.0f) * (1.0f / (float)IW);
    pyq[0] = 1.0f - (2.0f * (float)i0q + 1.0f) * (1.0f / (float)IH);
    pyq[1] = 1.0f - (2.0f * (float)(i0q + 1) + 1.0f) * (1.0f / (float)IH);
    // quad packed test word: passes iff face bbox intersects the 2x2 quad
    unsigned Pq = (unsigned)(j0 + 1) | ((unsigned)(i0q + 1) << 8)
                | ((unsigned)(127 - j0) << 16) | ((unsigned)(127 - i0q) << 24);
    unsigned Pp[4];
    #pragma unroll
    for (int p = 0; p < 4; p++) {
        int jj = j0 + (p & 1), ii = i0q + (p >> 1);
        Pp[p] = (unsigned)jj | ((unsigned)ii << 8)
              | ((unsigned)(127 - jj) << 16) | ((unsigned)(127 - ii) << 24);
    }

    const int CH = (NF + NSPLIT - 1) / NSPLIT;       // 79
    int fbeg = chunk * CH;
    int cnt = min(NF, fbeg + CH) - fbeg;

    // Phase A: compute this chunk's face records in-block (R13-proven bit-identical).
    if (tid == 0) nlist = 0;
    if (tid < cnt) {
        int f = fbeg + tid;
        int fi0 = faces[f * 3 + 0];
        int fi1 = faces[f * 3 + 1];
        int fi2 = faces[f * 3 + 2];
        const float* w0 = &verts[(b * NV + fi0) * 3];
        const float* w1 = &verts[(b * NV + fi1) * 3];
        const float* w2 = &verts[(b * NV + fi2) * 3];
        float3 p0 = xform(w0[0], w0[1], w0[2]);
        float3 p1 = xform(w1[0], w1[1], w1[2]);
        float3 p2 = xform(w2[0], w2[1], w2[2]);
        float v0x = p0.x, v0y = p0.y, t0 = p0.z;
        float v1x = p1.x, v1y = p1.y, t1 = p1.z;
        float v2x = p2.x, v2y = p2.y, t2 = p2.z;

        float area = (v1x - v0x) * (v2y - v0y) - (v1y - v0y) * (v2x - v0x);
        float areaS = (fabsf(area) < EPSV) ? EPSV : area;
        float invA  = 1.0f / areaS;
        bool  ok    = fabsf(area) > EPSV;
        float pad = 1e-5f;
        float xmn = fminf(v0x, fminf(v1x, v2x)) - pad;
        float xmx = fmaxf(v0x, fmaxf(v1x, v2x)) + pad;
        float ymn = fminf(v0y, fminf(v1y, v2y)) - pad;
        float ymx = fmaxf(v0y, fmaxf(v1y, v2y)) + pad;

        unsigned bb = 0xFFFFFFFFu;       // empty (degenerate): jmin=255 rejects all
        if (ok) {
            float jminf = fmaxf(0.0f, fminf(127.0f, ceilf(64.0f * (1.0f - xmx) - 0.5f) - 1.0f));
            float jmaxf = fmaxf(0.0f, fminf(127.0f, floorf(64.0f * (1.0f - xmn) - 0.5f) + 1.0f));
            float iminf = fmaxf(0.0f, fminf(127.0f, ceilf(64.0f * (1.0f - ymx) - 0.5f) - 1.0f));
            float imaxf = fmaxf(0.0f, fminf(127.0f, floorf(64.0f * (1.0f - ymn) - 0.5f) + 1.0f));
            unsigned jmin = (unsigned)jminf, jmax = (unsigned)jmaxf;
            unsigned imin = (unsigned)iminf, imax = (unsigned)imaxf;
            bb = jmin | (imin << 8) | ((127u - jmax) << 16) | ((127u - imax) << 24);
        }
        sbb[tid] = bb;
        sm[tid * 3 + 0] = make_float4(v0x, v0y, v1x, v1y);
        sm[tid * 3 + 1] = make_float4(v2x, v2y, invA, areaS);
        sm[tid * 3 + 2] = make_float4(1.0f / t0, 1.0f / t1, 1.0f / t2, 0.0f);
    }
    __syncthreads();

    // Phase B: order-preserving compaction on integer bbox vs 32x32 tile rect.
    {
        int k = tid;                      // CH=79 <= 256: single pass
        bool keep = false;
        unsigned bbw = 0;
        if (k < cnt) {
            bbw = sbb[k];
            int jmn = (int)(bbw & 255u), imn = (int)((bbw >> 8) & 255u);
            int jmx = 127 - (int)((bbw >> 16) & 255u);
            int imx = 127 - (int)((bbw >> 24) & 255u);
            keep = (jmn <= jx0 + 31) && (jmx >= jx0) && (imn <= iy0 + 31) && (imx >= iy0);
        }
        unsigned m = __ballot_sync(0xffffffffu, keep);
        if (lane == 0) warpcnt[warp] = __popc(m);
        __syncthreads();
        if (tid == 0) {
            int s = 0;
            #pragma unroll
            for (int w = 0; w < 8; w++) { warpoff[w] = s; s += warpcnt[w]; }
            nlist = s;
        }
        __syncthreads();
        if (keep) {
            int pos = warpoff[warp] + __popc(m & ((1u << lane) - 1u));
            cbb[pos] = bbw;
            cidx[pos] = (unsigned short)k;
        }
        __syncthreads();
    }
    int nl = nlist;

    float bestd[4], bestS[4];
    int bestf[4];
    #pragma unroll
    for (int p = 0; p < 4; p++) {
        bestd[p] = __int_as_float(0x7f800000);
        bestS[p] = EPSV;
        bestf[p] = -1;
    }

    for (int t = 0; t < nl; t++) {
        unsigned bbw = cbb[t];
        if (__vcmpgeu4(Pq, bbw) != 0xFFFFFFFFu) continue;   // quad-level reject
        int k = (int)cidx[t];
        float4 q0 = sm[k * 3 + 0];
        float4 q1 = sm[k * 3 + 1];
        float4 q2 = sm[k * 3 + 2];
        #pragma unroll
        for (int p = 0; p < 4; p++) {
            if (__vcmpgeu4(Pp[p], bbw) != 0xFFFFFFFFu) continue;  // per-pixel guard
            float px = pxq[p & 1];
            float py = pyq[p >> 1];
            // exact eval — verbatim R12/R13 machinery (reference expressions)
            float e0 = (q1.x - q0.z) * (py - q0.w) - (q1.y - q0.w) * (px - q0.z);
            float e1 = (q0.x - q1.x) * (py - q1.y) - (q0.y - q1.y) * (px - q1.x);
            float b0 = e0 * q1.z;          // sign-exact vs e0/areaS
            float b1 = e1 * q1.z;
            if (b0 >= 0.0f && b1 >= 0.0f) {
                float b2 = 1.0f - b0 - b1;
                bool inside;
                if (b2 > TAU)       inside = true;
                else if (b2 < -TAU) inside = false;
                else {             // boundary band: replicate reference divisions exactly
                    float bb0 = e0 / q1.w;
                    float bb1 = e1 / q1.w;
                    inside = (1.0f - bb0 - bb1) >= 0.0f;
                    b0 = bb0; b1 = bb1;
                }
                if (inside) {
                    float b2e = 1.0f - b0 - b1;
                    float S = b0 * q2.x + b1 * q2.y + b2e * q2.z;
                    if (S > bestS[p]) {
                        float d = 1.0f / fmaxf(S, EPSV);     // exact, only on updates
                        if (d < bestd[p]) { bestd[p] = d; bestS[p] = S; bestf[p] = fbeg + k; }
                    }
                }
            }
        }
    }

    #pragma unroll
    for (int p = 0; p < 4; p++) {
        if (bestf[p] >= 0) {
            int jj = j0 + (p & 1), ii = i0q + (p >> 1);
            unsigned long long key =
                ~(((unsigned long long)__float_as_uint(bestd[p]) << 32) | (unsigned)bestf[p]);
            atomicMax(&g_best[b][ii * IW + jj], key);
        }
    }
}

__global__ void k_shade(const float* __restrict__ verts, const int* __restrict__ faces,
                        float* __restrict__ out) {
    __shared__ int sOld;
    int idx = blockIdx.x * blockDim.x + threadIdx.x;
    int b = idx / (IH * IW);
    int pix = idx - b * (IH * IW);
    int i = pix / IW, j = pix - i * IW;
    float px = 1.0f - (2.0f * (float)j + 1.0f) * (1.0f / (float)IW);
    float py = 1.0f - (2.0f * (float)i + 1.0f) * (1.0f / (float)IH);

    unsigned long long key = g_best[b][pix];
    g_best[b][pix] = 0ull;                 // self-reset for next replay (own entry only)
    bool hit = (key != 0ull);
    float r = 1.0f, g = 1.0f, bl = 1.0f;
    if (hit) {
        int bestf = (int)((~key) & 0xFFFFFFFFull);
        int i0 = faces[bestf * 3 + 0];
        int i1 = faces[bestf * 3 + 1];
        int i2 = faces[bestf * 3 + 2];
        float a0x = g_vtx[b][i0][0], a0y = g_vtx[b][i0][1], t0 = g_vtx[b][i0][2];
        float a1x = g_vtx[b][i1][0], a1y = g_vtx[b][i1][1], t1 = g_vtx[b][i1][2];
        float a2x = g_vtx[b][i2][0], a2y = g_vtx[b][i2][1], t2 = g_vtx[b][i2][2];
        float ar = (a1x - a0x) * (a2y - a0y) - (a1y - a0y) * (a2x - a0x);
        if (fabsf(ar) < EPSV) ar = EPSV;
        float iar = __fdividef(1.0f, ar);
        float bb0 = ((a2x - a1x) * (py - a1y) - (a2y - a1y) * (px - a1x)) * iar;
        float bb1 = ((a0x - a2x) * (py - a2y) - (a0y - a2y) * (px - a2x)) * iar;
        float bb2 = 1.0f - bb0 - bb1;
        float w0 = __fdividef(bb0, t0), w1 = __fdividef(bb1, t1), w2 = __fdividef(bb2, t2);
        float is = __fdividef(1.0f, w0 + w1 + w2 + EPSV);
        float p0 = w0 * is, p1 = w1 * is, p2 = w2 * is;

        const float* wv0 = &verts[(b * NV + i0) * 3];
        const float* wv1 = &verts[(b * NV + i1) * 3];
        const float* wv2 = &verts[(b * NV + i2) * 3];
        float posx = p0 * wv0[0] + p1 * wv1[0] + p2 * wv2[0];
        float posy = p0 * wv0[1] + p1 * wv1[1] + p2 * wv2[1];
        float posz = p0 * wv0[2] + p1 * wv1[2] + p2 * wv2[2];

        float n0x = g_vn[b][i0][0], n0y = g_vn[b][i0][1], n0z = g_vn[b][i0][2];
        float n1x = g_vn[b][i1][0], n1y = g_vn[b][i1][1], n1z = g_vn[b][i1][2];
        float n2x = g_vn[b][i2][0], n2y = g_vn[b][i2][1], n2z = g_vn[b][i2][2];
        float r0 = __fdividef(1.0f, sqrtf(n0x * n0x + n0y * n0y + n0z * n0z) + EPSV);
        float r1 = __fdividef(1.0f, sqrtf(n1x * n1x + n1y * n1y + n1z * n1z) + EPSV);
        float r2 = __fdividef(1.0f, sqrtf(n2x * n2x + n2y * n2y + n2z * n2z) + EPSV);
        float nx = p0 * n0x * r0 + p1 * n1x * r1 + p2 * n2x * r2;
        float ny = p0 * n0y * r0 + p1 * n1y * r1 + p2 * n2y * r2;
        float nz = p0 * n0z * r0 + p1 * n1z * r1 + p2 * n2z * r2;
        float rn = __fdividef(1.0f, sqrtf(nx * nx + ny * ny + nz * nz) + EPSV);
        nx *= rn; ny *= rn; nz *= rn;

        float lx = 0.0f - posx, ly = 1.0f - posy, lz = 3.0f - posz;
        float rl = __fdividef(1.0f, sqrtf(lx * lx + ly * ly + lz * lz) + EPSV);
        lx *= rl; ly *= rl; lz *= rl;
        float vx = 0.0f - posx, vy = 0.0f - posy, vz = 2.0f - posz;
        float rv = __fdividef(1.0f, sqrtf(vx * vx + vy * vy + vz * vz) + EPSV);
        vx *= rv; vy *= rv; vz *= rv;

        float dnl = nx * lx + ny * ly + nz * lz;
        float ndl = fmaxf(dnl, 0.0f);
        float rx = 2.0f * dnl * nx - lx;
        float ry = 2.0f * dnl * ny - ly;
        float rz = 2.0f * dnl * nz - lz;
        float sc = fmaxf(rx * vx + ry * vy + rz * vz, 0.0f);
        float s2 = sc * sc, s4 = s2 * s2, s8 = s4 * s4;
        float spec = 0.2f * 0.6f * (s8 * s2);
        float shade = 0.5f + 0.3f * ndl;
        r  = (142.0f / 255.0f) * shade + spec;
        g  = (179.0f / 255.0f) * shade + spec;
        bl = (247.0f / 255.0f) * shade + spec;
    }
    int plane = IH * IW;
    out[(b * 3 + 0) * plane + pix] = r * 255.0f;
    out[(b * 3 + 1) * plane + pix] = g * 255.0f;
    out[(b * 3 + 2) * plane + pix] = bl * 255.0f;
    out[NB * 3 * plane + b * plane + pix] = hit ? 1.0f : 0.0f;

    // ---- tail: last block zeroes g_vn for the next replay (race-free: the
    // counter reaches gridDim.x-1 only after every block's g_vn reads are done) ----
    __syncthreads();
    if (threadIdx.x == 0) sOld = atomicAdd(&g_donecnt, 1);
    __syncthreads();
    if (sOld == (int)gridDim.x - 1) {
        float* vn = (float*)g_vn;
        for (int t = threadIdx.x; t < NB * NV * 3; t += 256) vn[t] = 0.0f;
        if (threadIdx.x == 0) g_donecnt = 0;
    }
}

extern "C" void kernel_launch(void* const* d_in, const int* in_sizes, int n_in,
                              void* d_out, int out_size) {
    const float* verts = (const float*)d_in[0];
    const int* faces = (const int*)d_in[1];
    float* out = (float*)d_out;

    dim3 grid(16, NB, NSPLIT + 1);
    k_render<<<grid, 256>>>(verts, faces);
    k_shade<<<(NB * IH * IW + 255) / 256, 256>>>(verts, faces, out);
}

// round 15
// speedup vs baseline: 1.1268x; 1.1268x over previous
#include <cuda_runtime.h>
#include <math.h>

#define NB 2
#define NV 1300
#define NF 2500
#define IH 128
#define IW 128
#define EPSV 1e-8f
#define NSPLIT 32
#define CHMAX 80    // ceil(2500/32)=79, rounded
#define TAU 1e-4f

// Scratch (allocation-free rule: __device__ globals; zero-initialized at load)
__device__ float g_vtx[NB][NV][3];              // ndcx, ndcy, viewz (for shade)
__device__ float g_vn[NB][NV][3];               // accumulated vertex normals (zeroed by shade tail)
// inverted keys: 0 = empty. key = ~((depthbits<<32)|face). atomicMax == min over (depth,face).
__device__ unsigned long long g_best[NB][IH * IW];
__device__ int g_donecnt;                       // shade-block completion counter

__device__ __noinline__ float3 xform(float x, float y, float z) {
    float vz = 2.0f - z;                 // view = verts @ diag(-1,1,-1) + (0,0,2)
    float nx = 12.0f * (-x) / vz;
    float ny = 12.0f * y / vz;
    return make_float3(nx, ny, vz);
}

// Single fused front kernel:
//  z-slice NSPLIT : vertex transform (g_vtx) + vertex-normal atomics (g_vn)
//  z-slices 0..31 : raster — 32x32 pixel tile per block, each thread sweeps its
//                   4 pixels as four sequential 16x16-quadrant passes with the
//                   VERBATIM R13 loop body (q2 loaded after the inside test —
//                   empirical law: this placement decides the fragile pixel).
__global__ void __launch_bounds__(256) k_render(const float* __restrict__ verts,
                                                const int* __restrict__ faces) {
    int tid = threadIdx.x;

    if (blockIdx.z == NSPLIT) {
        int idx = (blockIdx.y * gridDim.x + blockIdx.x) * 256 + tid;
        if (idx < NB * NV) {
            int b = idx / NV, v = idx - b * NV;
            float3 t = xform(verts[idx * 3 + 0], verts[idx * 3 + 1], verts[idx * 3 + 2]);
            g_vtx[b][v][0] = t.x;
            g_vtx[b][v][1] = t.y;
            g_vtx[b][v][2] = t.z;
        }
        if (idx < NB * NF) {
            int b = idx / NF, f = idx - b * NF;
            int i0 = faces[f * 3 + 0];
            int i1 = faces[f * 3 + 1];
            int i2 = faces[f * 3 + 2];
            const float* w0 = &verts[(b * NV + i0) * 3];
            const float* w1 = &verts[(b * NV + i1) * 3];
            const float* w2 = &verts[(b * NV + i2) * 3];
            float ax = w1[0] - w0[0], ay = w1[1] - w0[1], az = w1[2] - w0[2];
            float bx = w2[0] - w0[0], by = w2[1] - w0[1], bz = w2[2] - w0[2];
            float fx = ay * bz - az * by;
            float fy = az * bx - ax * bz;
            float fz = ax * by - ay * bx;
            atomicAdd(&g_vn[b][i0][0], fx); atomicAdd(&g_vn[b][i0][1], fy); atomicAdd(&g_vn[b][i0][2], fz);
            atomicAdd(&g_vn[b][i1][0], fx); atomicAdd(&g_vn[b][i1][1], fy); atomicAdd(&g_vn[b][i1][2], fz);
            atomicAdd(&g_vn[b][i2][0], fx); atomicAdd(&g_vn[b][i2][1], fy); atomicAdd(&g_vn[b][i2][2], fz);
        }
        return;
    }

    __shared__ float4 sm[CHMAX * 3];
    __shared__ unsigned sbb[CHMAX];
    __shared__ unsigned cbb[CHMAX];          // compacted bbox words (list order)
    __shared__ unsigned short cidx[CHMAX];   // compacted face indices (ascending)
    __shared__ int warpcnt[8];
    __shared__ int warpoff[8];
    __shared__ int nlist;

    int b = blockIdx.y;
    int chunk = blockIdx.z;
    int warp = tid >> 5, lane = tid & 31;
    // 32x32 tile: 4x4 tiles per image
    int jx0 = (blockIdx.x & 3) << 5;
    int iy0 = (blockIdx.x >> 2) << 5;

    const int CH = (NF + NSPLIT - 1) / NSPLIT;       // 79
    int fbeg = chunk * CH;
    int cnt = min(NF, fbeg + CH) - fbeg;

    // Phase A: compute this chunk's face records in-block (R13-proven bit-identical).
    if (tid == 0) nlist = 0;
    if (tid < cnt) {
        int f = fbeg + tid;
        int fi0 = faces[f * 3 + 0];
        int fi1 = faces[f * 3 + 1];
        int fi2 = faces[f * 3 + 2];
        const float* w0 = &verts[(b * NV + fi0) * 3];
        const float* w1 = &verts[(b * NV + fi1) * 3];
        const float* w2 = &verts[(b * NV + fi2) * 3];
        float3 p0 = xform(w0[0], w0[1], w0[2]);
        float3 p1 = xform(w1[0], w1[1], w1[2]);
        float3 p2 = xform(w2[0], w2[1], w2[2]);
        float v0x = p0.x, v0y = p0.y, t0 = p0.z;
        float v1x = p1.x, v1y = p1.y, t1 = p1.z;
        float v2x = p2.x, v2y = p2.y, t2 = p2.z;

        float area = (v1x - v0x) * (v2y - v0y) - (v1y - v0y) * (v2x - v0x);
        float areaS = (fabsf(area) < EPSV) ? EPSV : area;
        float invA  = 1.0f / areaS;
        bool  ok    = fabsf(area) > EPSV;
        float pad = 1e-5f;
        float xmn = fminf(v0x, fminf(v1x, v2x)) - pad;
        float xmx = fmaxf(v0x, fmaxf(v1x, v2x)) + pad;
        float ymn = fminf(v0y, fminf(v1y, v2y)) - pad;
        float ymx = fmaxf(v0y, fmaxf(v1y, v2y)) + pad;

        unsigned bb = 0xFFFFFFFFu;       // empty (degenerate): jmin=255 rejects all
        if (ok) {
            float jminf = fmaxf(0.0f, fminf(127.0f, ceilf(64.0f * (1.0f - xmx) - 0.5f) - 1.0f));
            float jmaxf = fmaxf(0.0f, fminf(127.0f, floorf(64.0f * (1.0f - xmn) - 0.5f) + 1.0f));
            float iminf = fmaxf(0.0f, fminf(127.0f, ceilf(64.0f * (1.0f - ymx) - 0.5f) - 1.0f));
            float imaxf = fmaxf(0.0f, fminf(127.0f, floorf(64.0f * (1.0f - ymn) - 0.5f) + 1.0f));
            unsigned jmin = (unsigned)jminf, jmax = (unsigned)jmaxf;
            unsigned imin = (unsigned)iminf, imax = (unsigned)imaxf;
            bb = jmin | (imin << 8) | ((127u - jmax) << 16) | ((127u - imax) << 24);
        }
        sbb[tid] = bb;
        sm[tid * 3 + 0] = make_float4(v0x, v0y, v1x, v1y);
        sm[tid * 3 + 1] = make_float4(v2x, v2y, invA, areaS);
        sm[tid * 3 + 2] = make_float4(1.0f / t0, 1.0f / t1, 1.0f / t2, 0.0f);
    }
    __syncthreads();

    // Phase B: order-preserving compaction on integer bbox vs 32x32 tile rect.
    {
        int k = tid;                      // CH=79 <= 256: single pass
        bool keep = false;
        unsigned bbw = 0;
        if (k < cnt) {
            bbw = sbb[k];
            int jmn = (int)(bbw & 255u), imn = (int)((bbw >> 8) & 255u);
            int jmx = 127 - (int)((bbw >> 16) & 255u);
            int imx = 127 - (int)((bbw >> 24) & 255u);
            keep = (jmn <= jx0 + 31) && (jmx >= jx0) && (imn <= iy0 + 31) && (imx >= iy0);
        }
        unsigned m = __ballot_sync(0xffffffffu, keep);
        if (lane == 0) warpcnt[warp] = __popc(m);
        __syncthreads();
        if (tid == 0) {
            int s = 0;
            #pragma unroll
            for (int w = 0; w < 8; w++) { warpoff[w] = s; s += warpcnt[w]; }
            nlist = s;
        }
        __syncthreads();
        if (keep) {
            int pos = warpoff[warp] + __popc(m & ((1u << lane) - 1u));
            cbb[pos] = bbw;
            cidx[pos] = (unsigned short)k;
        }
        __syncthreads();
    }
    int nl = nlist;
    if (nl == 0) return;

    // Four sequential 16x16-quadrant passes; scalar state per pass (no arrays).
    for (int q = 0; q < 4; q++) {
        int j = jx0 + ((q & 1) << 4) + (tid & 15);
        int i = iy0 + ((q >> 1) << 4) + (tid >> 4);
        float px = 1.0f - (2.0f * (float)j + 1.0f) * (1.0f / (float)IW);
        float py = 1.0f - (2.0f * (float)i + 1.0f) * (1.0f / (float)IH);
        unsigned P = (unsigned)j | ((unsigned)i << 8)
                   | ((unsigned)(127 - j) << 16) | ((unsigned)(127 - i) << 24);

        float bestd = __int_as_float(0x7f800000);
        float bestS = EPSV;
        int bestf = -1;

        for (int t = 0; t < nl; t++) {
            if (__vcmpgeu4(P, cbb[t]) != 0xFFFFFFFFu) continue;
            int k = (int)cidx[t];
            float4 q0 = sm[k * 3 + 0];
            float4 q1 = sm[k * 3 + 1];
            // exact eval — verbatim R13 machinery (reference expressions; q2 AFTER inside)
            float e0 = (q1.x - q0.z) * (py - q0.w) - (q1.y - q0.w) * (px - q0.z);
            float e1 = (q0.x - q1.x) * (py - q1.y) - (q0.y - q1.y) * (px - q1.x);
            float b0 = e0 * q1.z;          // sign-exact vs e0/areaS
            float b1 = e1 * q1.z;
            if (b0 >= 0.0f && b1 >= 0.0f) {
                float b2 = 1.0f - b0 - b1;
                bool inside;
                if (b2 > TAU)       inside = true;
                else if (b2 < -TAU) inside = false;
                else {             // boundary band: replicate reference divisions exactly
                    float bb0 = e0 / q1.w;
                    float bb1 = e1 / q1.w;
                    inside = (1.0f - bb0 - bb1) >= 0.0f;
                    b0 = bb0; b1 = bb1;
                }
                if (inside) {
                    float4 q2 = sm[k * 3 + 2];       // AFTER inside — do not move
                    float b2e = 1.0f - b0 - b1;
                    float S = b0 * q2.x + b1 * q2.y + b2e * q2.z;
                    if (S > bestS) {
                        float d = 1.0f / fmaxf(S, EPSV);     // exact, only on updates
                        if (d < bestd) { bestd = d; bestS = S; bestf = fbeg + k; }
                    }
                }
            }
        }

        if (bestf >= 0) {
            unsigned long long key =
                ~(((unsigned long long)__float_as_uint(bestd) << 32) | (unsigned)bestf);
            atomicMax(&g_best[b][i * IW + j], key);
        }
    }
}

__global__ void k_shade(const float* __restrict__ verts, const int* __restrict__ faces,
                        float* __restrict__ out) {
    __shared__ int sOld;
    int idx = blockIdx.x * blockDim.x + threadIdx.x;
    int b = idx / (IH * IW);
    int pix = idx - b * (IH * IW);
    int i = pix / IW, j = pix - i * IW;
    float px = 1.0f - (2.0f * (float)j + 1.0f) * (1.0f / (float)IW);
    float py = 1.0f - (2.0f * (float)i + 1.0f) * (1.0f / (float)IH);

    unsigned long long key = g_best[b][pix];
    g_best[b][pix] = 0ull;                 // self-reset for next replay (own entry only)
    bool hit = (key != 0ull);
    float r = 1.0f, g = 1.0f, bl = 1.0f;
    if (hit) {
        int bestf = (int)((~key) & 0xFFFFFFFFull);
        int i0 = faces[bestf * 3 + 0];
        int i1 = faces[bestf * 3 + 1];
        int i2 = faces[bestf * 3 + 2];
        float a0x = g_vtx[b][i0][0], a0y = g_vtx[b][i0][1], t0 = g_vtx[b][i0][2];
        float a1x = g_vtx[b][i1][0], a1y = g_vtx[b][i1][1], t1 = g_vtx[b][i1][2];
        float a2x = g_vtx[b][i2][0], a2y = g_vtx[b][i2][1], t2 = g_vtx[b][i2][2];
        float ar = (a1x - a0x) * (a2y - a0y) - (a1y - a0y) * (a2x - a0x);
        if (fabsf(ar) < EPSV) ar = EPSV;
        float iar = __fdividef(1.0f, ar);
        float bb0 = ((a2x - a1x) * (py - a1y) - (a2y - a1y) * (px - a1x)) * iar;
        float bb1 = ((a0x - a2x) * (py - a2y) - (a0y - a2y) * (px - a2x)) * iar;
        float bb2 = 1.0f - bb0 - bb1;
        float w0 = __fdividef(bb0, t0), w1 = __fdividef(bb1, t1), w2 = __fdividef(bb2, t2);
        float is = __fdividef(1.0f, w0 + w1 + w2 + EPSV);
        float p0 = w0 * is, p1 = w1 * is, p2 = w2 * is;

        const float* wv0 = &verts[(b * NV + i0) * 3];
        const float* wv1 = &verts[(b * NV + i1) * 3];
        const float* wv2 = &verts[(b * NV + i2) * 3];
        float posx = p0 * wv0[0] + p1 * wv1[0] + p2 * wv2[0];
        float posy = p0 * wv0[1] + p1 * wv1[1] + p2 * wv2[1];
        float posz = p0 * wv0[2] + p1 * wv1[2] + p2 * wv2[2];

        float n0x = g_vn[b][i0][0], n0y = g_vn[b][i0][1], n0z = g_vn[b][i0][2];
        float n1x = g_vn[b][i1][0], n1y = g_vn[b][i1][1], n1z = g_vn[b][i1][2];
        float n2x = g_vn[b][i2][0], n2y = g_vn[b][i2][1], n2z = g_vn[b][i2][2];
        float r0 = __fdividef(1.0f, sqrtf(n0x * n0x + n0y * n0y + n0z * n0z) + EPSV);
        float r1 = __fdividef(1.0f, sqrtf(n1x * n1x + n1y * n1y + n1z * n1z) + EPSV);
        float r2 = __fdividef(1.0f, sqrtf(n2x * n2x + n2y * n2y + n2z * n2z) + EPSV);
        float nx = p0 * n0x * r0 + p1 * n1x * r1 + p2 * n2x * r2;
        float ny = p0 * n0y * r0 + p1 * n1y * r1 + p2 * n2y * r2;
        float nz = p0 * n0z * r0 + p1 * n1z * r1 + p2 * n2z * r2;
        float rn = __fdividef(1.0f, sqrtf(nx * nx + ny * ny + nz * nz) + EPSV);
        nx *= rn; ny *= rn; nz *= rn;

        float lx = 0.0f - posx, ly = 1.0f - posy, lz = 3.0f - posz;
        float rl = __fdividef(1.0f, sqrtf(lx * lx + ly * ly + lz * lz) + EPSV);
        lx *= rl; ly *= rl; lz *= rl;
        float vx = 0.0f - posx, vy = 0.0f - posy, vz = 2.0f - posz;
        float rv = __fdividef(1.0f, sqrtf(vx * vx + vy * vy + vz * vz) + EPSV);
        vx *= rv; vy *= rv; vz *= rv;

        float dnl = nx * lx + ny * ly + nz * lz;
        float ndl = fmaxf(dnl, 0.0f);
        float rx = 2.0f * dnl * nx - lx;
        float ry = 2.0f * dnl * ny - ly;
        float rz = 2.0f * dnl * nz - lz;
        float sc = fmaxf(rx * vx + ry * vy + rz * vz, 0.0f);
        float s2 = sc * sc, s4 = s2 * s2, s8 = s4 * s4;
        float spec = 0.2f * 0.6f * (s8 * s2);
        float shade = 0.5f + 0.3f * ndl;
        r  = (142.0f / 255.0f) * shade + spec;
        g  = (179.0f / 255.0f) * shade + spec;
        bl = (247.0f / 255.0f) * shade + spec;
    }
    int plane = IH * IW;
    out[(b * 3 + 0) * plane + pix] = r * 255.0f;
    out[(b * 3 + 1) * plane + pix] = g * 255.0f;
    out[(b * 3 + 2) * plane + pix] = bl * 255.0f;
    out[NB * 3 * plane + b * plane + pix] = hit ? 1.0f : 0.0f;

    // ---- tail: last block zeroes g_vn for the next replay (race-free: the
    // counter reaches gridDim.x-1 only after every block's g_vn reads are done) ----
    __syncthreads();
    if (threadIdx.x == 0) sOld = atomicAdd(&g_donecnt, 1);
    __syncthreads();
    if (sOld == (int)gridDim.x - 1) {
        float* vn = (float*)g_vn;
        for (int t = threadIdx.x; t < NB * NV * 3; t += 256) vn[t] = 0.0f;
        if (threadIdx.x == 0) g_donecnt = 0;
    }
}

extern "C" void kernel_launch(void* const* d_in, const int* in_sizes, int n_in,
                              void* d_out, int out_size) {
    const float* verts = (const float*)d_in[0];
    const int* faces = (const int*)d_in[1];
    float* out = (float*)d_out;

    dim3 grid(16, NB, NSPLIT + 1);
    k_render<<<grid, 256>>>(verts, faces);
    k_shade<<<(NB * IH * IW + 255) / 256, 256>>>(verts, faces, out);
}

// round 16
// speedup vs baseline: 1.6463x; 1.4610x over previous
#include <cuda_runtime.h>
#include <math.h>

#define NB 2
#define NV 1300
#define NF 2500
#define IH 128
#define IW 128
#define EPSV 1e-8f
#define NSPLIT 32
#define CHMAX 80    // ceil(2500/32)=79, rounded
#define TAU 1e-4f

// Scratch (allocation-free rule: __device__ globals; zero-initialized at load)
__device__ float    g_vtx[NB][NV][3];           // ndcx, ndcy, viewz
__device__ float    g_vn[NB][NV][3];            // accumulated vertex normals
__device__ float    g_fn[NB][NF][3];            // per-face world normals
__device__ float4   g_fd[NB][NF * 3];           // per-face packed raster data (3 slots)
__device__ unsigned g_fbb[NB][NF];              // packed pixel-space bbox per face
// inverted keys: 0 = empty. key = ~((depthbits<<32)|face). atomicMax == min over (depth,face).
__device__ unsigned long long g_best[NB][IH * IW];

__device__ __noinline__ float3 xform(float x, float y, float z) {
    float vz = 2.0f - z;                 // view = verts @ diag(-1,1,-1) + (0,0,2)
    float nx = 12.0f * (-x) / vz;
    float ny = 12.0f * y / vz;
    return make_float3(nx, ny, vz);
}

// Prep: vertex transform + vn zero + face raster data + face normals + packed bbox.
// (vn ZEROING here is safe: accumulation happens in k_render's z-slice — a later kernel.)
__global__ void k_prep(const float* __restrict__ verts, const int* __restrict__ faces) {
    int idx = blockIdx.x * blockDim.x + threadIdx.x;
    if (idx < NB * NV) {
        int b = idx / NV, v = idx - b * NV;
        float3 t = xform(verts[idx * 3 + 0], verts[idx * 3 + 1], verts[idx * 3 + 2]);
        g_vtx[b][v][0] = t.x;
        g_vtx[b][v][1] = t.y;
        g_vtx[b][v][2] = t.z;
        g_vn[b][v][0] = 0.0f; g_vn[b][v][1] = 0.0f; g_vn[b][v][2] = 0.0f;
    }
    if (idx < NB * NF) {
        int b = idx / NF, f = idx - b * NF;
        int i0 = faces[f * 3 + 0];
        int i1 = faces[f * 3 + 1];
        int i2 = faces[f * 3 + 2];
        const float* w0 = &verts[(b * NV + i0) * 3];
        const float* w1 = &verts[(b * NV + i1) * 3];
        const float* w2 = &verts[(b * NV + i2) * 3];
        float w0x = w0[0], w0y = w0[1], w0z = w0[2];
        float w1x = w1[0], w1y = w1[1], w1z = w1[2];
        float w2x = w2[0], w2y = w2[1], w2z = w2[2];
        float ax = w1x - w0x, ay = w1y - w0y, az = w1z - w0z;
        float bx = w2x - w0x, by = w2y - w0y, bz = w2z - w0z;
        g_fn[b][f][0] = ay * bz - az * by;
        g_fn[b][f][1] = az * bx - ax * bz;
        g_fn[b][f][2] = ax * by - ay * bx;

        float3 p0 = xform(w0x, w0y, w0z);
        float3 p1 = xform(w1x, w1y, w1z);
        float3 p2 = xform(w2x, w2y, w2z);
        float v0x = p0.x, v0y = p0.y, t0 = p0.z;
        float v1x = p1.x, v1y = p1.y, t1 = p1.z;
        float v2x = p2.x, v2y = p2.y, t2 = p2.z;

        float area = (v1x - v0x) * (v2y - v0y) - (v1y - v0y) * (v2x - v0x);
        float areaS = (fabsf(area) < EPSV) ? EPSV : area;
        float invA  = 1.0f / areaS;
        bool  ok    = fabsf(area) > EPSV;
        float pad = 1e-5f;
        float xmn = fminf(v0x, fminf(v1x, v2x)) - pad;
        float xmx = fmaxf(v0x, fmaxf(v1x, v2x)) + pad;
        float ymn = fminf(v0y, fminf(v1y, v2y)) - pad;
        float ymx = fmaxf(v0y, fmaxf(v1y, v2y)) + pad;

        // conservative pixel-space bbox (superset of the float bbox; +-1 px margin)
        unsigned bb = 0xFFFFFFFFu;       // empty (degenerate): jmin=255 rejects all
        if (ok) {
            float jminf = fmaxf(0.0f, fminf(127.0f, ceilf(64.0f * (1.0f - xmx) - 0.5f) - 1.0f));
            float jmaxf = fmaxf(0.0f, fminf(127.0f, floorf(64.0f * (1.0f - xmn) - 0.5f) + 1.0f));
            float iminf = fmaxf(0.0f, fminf(127.0f, ceilf(64.0f * (1.0f - ymx) - 0.5f) - 1.0f));
            float imaxf = fmaxf(0.0f, fminf(127.0f, floorf(64.0f * (1.0f - ymn) - 0.5f) + 1.0f));
            unsigned jmin = (unsigned)jminf, jmax = (unsigned)jmaxf;
            unsigned imin = (unsigned)iminf, imax = (unsigned)imaxf;
            bb = jmin | (imin << 8) | ((127u - jmax) << 16) | ((127u - imax) << 24);
        }
        g_fbb[b][f] = bb;
        g_fd[b][f * 3 + 0] = make_float4(v0x, v0y, v1x, v1y);
        g_fd[b][f * 3 + 1] = make_float4(v2x, v2y, invA, areaS);
        g_fd[b][f * 3 + 2] = make_float4(1.0f / t0, 1.0f / t1, 1.0f / t2, 0.0f);
    }
}

__global__ void __launch_bounds__(256) k_render(const int* __restrict__ faces) {
    int tid = threadIdx.x;

    // z-slice NSPLIT: vertex-normal atomic accumulation (runs after k_prep's zeroing)
    if (blockIdx.z == NSPLIT) {
        int lid = blockIdx.y * gridDim.x + blockIdx.x;
        int idx = lid * 256 + tid;
        if (idx < NB * NF) {
            int b = idx / NF, f = idx - b * NF;
            float fx = g_fn[b][f][0], fy = g_fn[b][f][1], fz = g_fn[b][f][2];
            int i0 = faces[f * 3 + 0];
            int i1 = faces[f * 3 + 1];
            int i2 = faces[f * 3 + 2];
            atomicAdd(&g_vn[b][i0][0], fx); atomicAdd(&g_vn[b][i0][1], fy); atomicAdd(&g_vn[b][i0][2], fz);
            atomicAdd(&g_vn[b][i1][0], fx); atomicAdd(&g_vn[b][i1][1], fy); atomicAdd(&g_vn[b][i1][2], fz);
            atomicAdd(&g_vn[b][i2][0], fx); atomicAdd(&g_vn[b][i2][1], fy); atomicAdd(&g_vn[b][i2][2], fz);
        }
        return;
    }

    __shared__ float4 sm[CHMAX * 3];
    __shared__ unsigned sbb[CHMAX];
    __shared__ unsigned cbb[CHMAX];          // compacted bbox words (list order)
    __shared__ unsigned short cidx[CHMAX];   // compacted face indices (ascending)
    __shared__ int warpcnt[8];
    __shared__ int warpoff[8];
    __shared__ int nlist;

    int b = blockIdx.y;
    int chunk = blockIdx.z;
    int warp = tid >> 5, lane = tid & 31;
    int jx0 = (blockIdx.x & 7) << 4;
    int iy0 = (blockIdx.x >> 3) << 4;
    int j = jx0 + (tid & 15);
    int i = iy0 + (tid >> 4);
    float px = 1.0f - (2.0f * (float)j + 1.0f) * (1.0f / (float)IW);
    float py = 1.0f - (2.0f * (float)i + 1.0f) * (1.0f / (float)IH);
    unsigned P = (unsigned)j | ((unsigned)i << 8)
               | ((unsigned)(127 - j) << 16) | ((unsigned)(127 - i) << 24);

    const int CH = (NF + NSPLIT - 1) / NSPLIT;       // 79
    int fbeg = chunk * CH;
    int cnt = min(NF, fbeg + CH) - fbeg;

    const float4* fd = g_fd[b];
    for (int k = tid; k < cnt * 3; k += 256) sm[k] = fd[fbeg * 3 + k];
    for (int k = tid; k < cnt; k += 256) sbb[k] = g_fbb[b][fbeg + k];
    if (tid == 0) nlist = 0;
    __syncthreads();

    // Order-preserving compaction on integer bbox vs tile rect.
    {
        int k = tid;                      // CH=79 <= 256: single pass
        bool keep = false;
        unsigned bbw = 0;
        if (k < cnt) {
            bbw = sbb[k];
            int jmn = (int)(bbw & 255u), imn = (int)((bbw >> 8) & 255u);
            int jmx = 127 - (int)((bbw >> 16) & 255u);
            int imx = 127 - (int)((bbw >> 24) & 255u);
            keep = (jmn <= jx0 + 15) && (jmx >= jx0) && (imn <= iy0 + 15) && (imx >= iy0);
        }
        unsigned m = __ballot_sync(0xffffffffu, keep);
        if (lane == 0) warpcnt[warp] = __popc(m);
        __syncthreads();
        if (tid == 0) {
            int s = 0;
            #pragma unroll
            for (int w = 0; w < 8; w++) { warpoff[w] = s; s += warpcnt[w]; }
            nlist = s;
        }
        __syncthreads();
        if (keep) {
            int pos = warpoff[warp] + __popc(m & ((1u << lane) - 1u));
            cbb[pos] = bbw;
            cidx[pos] = (unsigned short)k;
        }
        __syncthreads();
    }
    int nl = nlist;

    float bestd = __int_as_float(0x7f800000);
    float bestS = EPSV;
    int bestf = -1;

    for (int t = 0; t < nl; t++) {
        // integer bbox test: all 4 bytes of P >= corresponding bytes of bb
        if (__vcmpgeu4(P, cbb[t]) != 0xFFFFFFFFu) continue;
        int k = (int)cidx[t];
        float4 q0 = sm[k * 3 + 0];
        float4 q1 = sm[k * 3 + 1];
        // exact eval — champion machinery (reference expressions; q2 AFTER inside)
        float e0 = (q1.x - q0.z) * (py - q0.w) - (q1.y - q0.w) * (px - q0.z);
        float e1 = (q0.x - q1.x) * (py - q1.y) - (q0.y - q1.y) * (px - q1.x);
        float b0 = e0 * q1.z;          // sign-exact vs e0/areaS
        float b1 = e1 * q1.z;
        if (b0 >= 0.0f && b1 >= 0.0f) {
            float b2 = 1.0f - b0 - b1;
            bool inside;
            if (b2 > TAU)       inside = true;
            else if (b2 < -TAU) inside = false;
            else {             // boundary band: replicate reference divisions exactly
                float bb0 = e0 / q1.w;
                float bb1 = e1 / q1.w;
                inside = (1.0f - bb0 - bb1) >= 0.0f;
                b0 = bb0; b1 = bb1;
            }
            if (inside) {
                float4 q2 = sm[k * 3 + 2];       // AFTER inside — do not move
                float b2e = 1.0f - b0 - b1;
                float S = b0 * q2.x + b1 * q2.y + b2e * q2.z;
                if (S > bestS) {
                    float d = 1.0f / fmaxf(S, EPSV);     // exact, only on updates
                    if (d < bestd) { bestd = d; bestS = S; bestf = fbeg + k; }
                }
            }
        }
    }

    if (bestf >= 0) {
        unsigned long long key =
            ~(((unsigned long long)__float_as_uint(bestd) << 32) | (unsigned)bestf);
        atomicMax(&g_best[b][i * IW + j], key);
    }
}

__global__ void k_shade(const float* __restrict__ verts, const int* __restrict__ faces,
                        float* __restrict__ out) {
    int idx = blockIdx.x * blockDim.x + threadIdx.x;
    if (idx >= NB * IH * IW) return;
    int b = idx / (IH * IW);
    int pix = idx - b * (IH * IW);
    int i = pix / IW, j = pix - i * IW;
    float px = 1.0f - (2.0f * (float)j + 1.0f) * (1.0f / (float)IW);
    float py = 1.0f - (2.0f * (float)i + 1.0f) * (1.0f / (float)IH);

    unsigned long long key = g_best[b][pix];
    g_best[b][pix] = 0ull;                 // self-reset for next replay (own entry only)
    bool hit = (key != 0ull);
    float r = 1.0f, g = 1.0f, bl = 1.0f;
    if (hit) {
        int bestf = (int)((~key) & 0xFFFFFFFFull);
        int i0 = faces[bestf * 3 + 0];
        int i1 = faces[bestf * 3 + 1];
        int i2 = faces[bestf * 3 + 2];
        float a0x = g_vtx[b][i0][0], a0y = g_vtx[b][i0][1], t0 = g_vtx[b][i0][2];
        float a1x = g_vtx[b][i1][0], a1y = g_vtx[b][i1][1], t1 = g_vtx[b][i1][2];
        float a2x = g_vtx[b][i2][0], a2y = g_vtx[b][i2][1], t2 = g_vtx[b][i2][2];
        float ar = (a1x - a0x) * (a2y - a0y) - (a1y - a0y) * (a2x - a0x);
        if (fabsf(ar) < EPSV) ar = EPSV;
        // exact IEEE divisions (champion shade math)
        float bb0 = ((a2x - a1x) * (py - a1y) - (a2y - a1y) * (px - a1x)) / ar;
        float bb1 = ((a0x - a2x) * (py - a2y) - (a0y - a2y) * (px - a2x)) / ar;
        float bb2 = 1.0f - bb0 - bb1;
        float w0 = bb0 / t0, w1 = bb1 / t1, w2 = bb2 / t2;
        float s = w0 + w1 + w2 + EPSV;
        float p0 = w0 / s, p1 = w1 / s, p2 = w2 / s;

        const float* wv0 = &verts[(b * NV + i0) * 3];
        const float* wv1 = &verts[(b * NV + i1) * 3];
        const float* wv2 = &verts[(b * NV + i2) * 3];
        float posx = p0 * wv0[0] + p1 * wv1[0] + p2 * wv2[0];
        float posy = p0 * wv0[1] + p1 * wv1[1] + p2 * wv2[1];
        float posz = p0 * wv0[2] + p1 * wv1[2] + p2 * wv2[2];

        float n0x = g_vn[b][i0][0], n0y = g_vn[b][i0][1], n0z = g_vn[b][i0][2];
        float n1x = g_vn[b][i1][0], n1y = g_vn[b][i1][1], n1z = g_vn[b][i1][2];
        float n2x = g_vn[b][i2][0], n2y = g_vn[b][i2][1], n2z = g_vn[b][i2][2];
        float n0 = sqrtf(n0x * n0x + n0y * n0y + n0z * n0z) + EPSV;
        float n1 = sqrtf(n1x * n1x + n1y * n1y + n1z * n1z) + EPSV;
        float n2 = sqrtf(n2x * n2x + n2y * n2y + n2z * n2z) + EPSV;
        n0x /= n0; n0y /= n0; n0z /= n0;
        n1x /= n1; n1y /= n1; n1z /= n1;
        n2x /= n2; n2y /= n2; n2z /= n2;

        float nx = p0 * n0x + p1 * n1x + p2 * n2x;
        float ny = p0 * n0y + p1 * n1y + p2 * n2y;
        float nz = p0 * n0z + p1 * n1z + p2 * n2z;
        float nn = sqrtf(nx * nx + ny * ny + nz * nz) + EPSV;
        nx /= nn; ny /= nn; nz /= nn;

        float lx = 0.0f - posx, ly = 1.0f - posy, lz = 3.0f - posz;
        float ln = sqrtf(lx * lx + ly * ly + lz * lz) + EPSV;
        lx /= ln; ly /= ln; lz /= ln;
        float vx = 0.0f - posx, vy = 0.0f - posy, vz = 2.0f - posz;
        float vnm = sqrtf(vx * vx + vy * vy + vz * vz) + EPSV;
        vx /= vnm; vy /= vnm; vz /= vnm;

        float dnl = nx * lx + ny * ly + nz * lz;
        float ndl = fmaxf(dnl, 0.0f);
        float rx = 2.0f * dnl * nx - lx;
        float ry = 2.0f * dnl * ny - ly;
        float rz = 2.0f * dnl * nz - lz;
        float sc = fmaxf(rx * vx + ry * vy + rz * vz, 0.0f);
        float s2 = sc * sc, s4 = s2 * s2, s8 = s4 * s4;
        float spec = 0.2f * 0.6f * (s8 * s2);
        float shade = 0.5f + 0.3f * ndl;
        r  = (142.0f / 255.0f) * shade + spec;
        g  = (179.0f / 255.0f) * shade + spec;
        bl = (247.0f / 255.0f) * shade + spec;
    }
    int plane = IH * IW;
    out[(b * 3 + 0) * plane + pix] = r * 255.0f;
    out[(b * 3 + 1) * plane + pix] = g * 255.0f;
    out[(b * 3 + 2) * plane + pix] = bl * 255.0f;
    out[NB * 3 * plane + b * plane + pix] = hit ? 1.0f : 0.0f;
}

extern "C" void kernel_launch(void* const* d_in, const int* in_sizes, int n_in,
                              void* d_out, int out_size) {
    const float* verts = (const float*)d_in[0];
    const int* faces = (const int*)d_in[1];
    float* out = (float*)d_out;

    k_prep<<<(NB * NF + 255) / 256, 256>>>(verts, faces);
    dim3 grid(64, NB, NSPLIT + 1);
    k_render<<<grid, 256>>>(faces);
    k_shade<<<(NB * IH * IW + 255) / 256, 256>>>(verts, faces, out);
}

// round 17
// speedup vs baseline: 1.7303x; 1.0510x over previous
#include <cuda_runtime.h>
#include <math.h>

#define NB 2
#define NV 1300
#define NF 2500
#define IH 128
#define IW 128
#define EPSV 1e-8f
#define NSPLIT 32
#define CHMAX 80    // ceil(2500/32)=79, rounded
#define TAU 1e-4f

// Scratch (allocation-free rule: __device__ globals; zero-initialized at load)
__device__ float  g_vtx[NB][NV][3];             // ndcx, ndcy, viewz
__device__ float  g_vn[NB][NV][3];              // accumulated vertex normals
__device__ float  g_fn[NB][NF][3];              // per-face world normals
__device__ float4 g_fd[NB][NF * 4];             // per-face packed raster data
// inverted keys: 0 = empty. key = ~((depthbits<<32)|face). atomicMax == min over (depth,face).
__device__ unsigned long long g_best[NB][IH * IW];

__device__ __noinline__ float3 xform(float x, float y, float z) {
    float vz = 2.0f - z;                 // view = verts @ diag(-1,1,-1) + (0,0,2)
    float nx = 12.0f * (-x) / vz;
    float ny = 12.0f * y / vz;
    return make_float3(nx, ny, vz);
}

// Fused prep: vertex transform + vn zero + face raster data + face normals
__global__ void k_prep(const float* __restrict__ verts, const int* __restrict__ faces) {
    int idx = blockIdx.x * blockDim.x + threadIdx.x;
    if (idx < NB * NV) {
        int b = idx / NV, v = idx - b * NV;
        float3 t = xform(verts[idx * 3 + 0], verts[idx * 3 + 1], verts[idx * 3 + 2]);
        g_vtx[b][v][0] = t.x;
        g_vtx[b][v][1] = t.y;
        g_vtx[b][v][2] = t.z;
        g_vn[b][v][0] = 0.0f; g_vn[b][v][1] = 0.0f; g_vn[b][v][2] = 0.0f;
    }
    if (idx < NB * NF) {
        int b = idx / NF, f = idx - b * NF;
        int i0 = faces[f * 3 + 0];
        int i1 = faces[f * 3 + 1];
        int i2 = faces[f * 3 + 2];
        const float* w0 = &verts[(b * NV + i0) * 3];
        const float* w1 = &verts[(b * NV + i1) * 3];
        const float* w2 = &verts[(b * NV + i2) * 3];
        float w0x = w0[0], w0y = w0[1], w0z = w0[2];
        float w1x = w1[0], w1y = w1[1], w1z = w1[2];
        float w2x = w2[0], w2y = w2[1], w2z = w2[2];
        float ax = w1x - w0x, ay = w1y - w0y, az = w1z - w0z;
        float bx = w2x - w0x, by = w2y - w0y, bz = w2z - w0z;
        g_fn[b][f][0] = ay * bz - az * by;
        g_fn[b][f][1] = az * bx - ax * bz;
        g_fn[b][f][2] = ax * by - ay * bx;

        float3 p0 = xform(w0x, w0y, w0z);
        float3 p1 = xform(w1x, w1y, w1z);
        float3 p2 = xform(w2x, w2y, w2z);
        float v0x = p0.x, v0y = p0.y, t0 = p0.z;
        float v1x = p1.x, v1y = p1.y, t1 = p1.z;
        float v2x = p2.x, v2y = p2.y, t2 = p2.z;

        float area = (v1x - v0x) * (v2y - v0y) - (v1y - v0y) * (v2x - v0x);
        float areaS = (fabsf(area) < EPSV) ? EPSV : area;
        float invA  = 1.0f / areaS;
        bool  ok    = fabsf(area) > EPSV;
        float pad = 1e-5f;
        float xmn = fminf(v0x, fminf(v1x, v2x)) - pad;
        float xmx = fmaxf(v0x, fmaxf(v1x, v2x)) + pad;
        float ymn = fminf(v0y, fminf(v1y, v2y)) - pad;
        float ymx = fmaxf(v0y, fmaxf(v1y, v2y)) + pad;
        if (!ok) { xmn = 1e30f; xmx = -1e30f; }   // degenerate: empty bbox
        float minz = fminf(t0, fminf(t1, t2));
        g_fd[b][f * 4 + 0] = make_float4(v0x, v0y, v1x, v1y);
        g_fd[b][f * 4 + 1] = make_float4(v2x, v2y, invA, areaS);
        g_fd[b][f * 4 + 2] = make_float4(1.0f / t0, 1.0f / t1, 1.0f / t2, minz);
        g_fd[b][f * 4 + 3] = make_float4(xmn, xmx, ymn, ymx);
    }
}

__global__ void __launch_bounds__(256) k_render(const int* __restrict__ faces) {
    int tid = threadIdx.x;

    // z-slice NSPLIT: vertex-normal atomic accumulation (independent work)
    if (blockIdx.z == NSPLIT) {
        int lid = blockIdx.y * gridDim.x + blockIdx.x;
        int idx = lid * 256 + tid;
        if (idx < NB * NF) {
            int b = idx / NF, f = idx - b * NF;
            float fx = g_fn[b][f][0], fy = g_fn[b][f][1], fz = g_fn[b][f][2];
            int i0 = faces[f * 3 + 0];
            int i1 = faces[f * 3 + 1];
            int i2 = faces[f * 3 + 2];
            atomicAdd(&g_vn[b][i0][0], fx); atomicAdd(&g_vn[b][i0][1], fy); atomicAdd(&g_vn[b][i0][2], fz);
            atomicAdd(&g_vn[b][i1][0], fx); atomicAdd(&g_vn[b][i1][1], fy); atomicAdd(&g_vn[b][i1][2], fz);
            atomicAdd(&g_vn[b][i2][0], fx); atomicAdd(&g_vn[b][i2][1], fy); atomicAdd(&g_vn[b][i2][2], fz);
        }
        return;
    }

    __shared__ float4 sm[CHMAX * 4];
    __shared__ float sminz[CHMAX];
    __shared__ unsigned short list[CHMAX];
    __shared__ int warpcnt[8];
    __shared__ int warpoff[8];
    __shared__ int nlist;

    int b = blockIdx.y;
    int chunk = blockIdx.z;
    int warp = tid >> 5, lane = tid & 31;
    int jx0 = (blockIdx.x & 7) << 4;
    int iy0 = (blockIdx.x >> 3) << 4;
    int j = jx0 + (tid & 15);
    int i = iy0 + (tid >> 4);
    float px = 1.0f - (2.0f * (float)j + 1.0f) * (1.0f / (float)IW);
    float py = 1.0f - (2.0f * (float)i + 1.0f) * (1.0f / (float)IH);
    float tpx_hi = 1.0f - (2.0f * (float)jx0 + 1.0f) * (1.0f / (float)IW);
    float tpx_lo = 1.0f - (2.0f * (float)(jx0 + 15) + 1.0f) * (1.0f / (float)IW);
    float tpy_hi = 1.0f - (2.0f * (float)iy0 + 1.0f) * (1.0f / (float)IH);
    float tpy_lo = 1.0f - (2.0f * (float)(iy0 + 15) + 1.0f) * (1.0f / (float)IH);

    const int CH = (NF + NSPLIT - 1) / NSPLIT;       // 79
    int fbeg = chunk * CH;
    int cnt = min(NF, fbeg + CH) - fbeg;

    const float4* fd = g_fd[b];
    for (int k = tid; k < cnt * 4; k += 256) sm[k] = fd[fbeg * 4 + k];
    if (tid == 0) nlist = 0;
    __syncthreads();
    for (int k = tid; k < cnt; k += 256) sminz[k] = sm[k * 4 + 2].w;

    // Order-preserving compaction: faces whose bbox intersects the tile rect.
    {
        int k = tid;                      // CH=79 <= 256: single pass
        bool keep = false;
        if (k < cnt) {
            float4 bb = sm[k * 4 + 3];
            keep = (bb.x <= tpx_hi) & (bb.y >= tpx_lo) & (bb.z <= tpy_hi) & (bb.w >= tpy_lo);
        }
        unsigned m = __ballot_sync(0xffffffffu, keep);
        if (lane == 0) warpcnt[warp] = __popc(m);
        __syncthreads();
        if (tid == 0) {
            int s = 0;
            #pragma unroll
            for (int w = 0; w < 8; w++) { warpoff[w] = s; s += warpcnt[w]; }
            nlist = s;
        }
        __syncthreads();
        if (keep) {
            int pos = warpoff[warp] + __popc(m & ((1u << lane) - 1u));
            list[pos] = (unsigned short)k;
        }
        __syncthreads();
    }
    int nl = nlist;

    // Cross-chunk early-z: snapshot is PRUNE-ONLY. Skipped face has final
    // d >= minz*(1-1e-6) > min(pruneD,bestd)*(1+~1e-3): strictly worse than
    // both the local best and the committed global key (ties included) —
    // outcome-identical. q2 is loaded ONLY after the inside test (the law).
    int pix = i * IW + j;
    unsigned long long snap = g_best[b][pix];
    float pruneD = __int_as_float(0x7f800000);
    if (snap != 0ull) pruneD = __uint_as_float((unsigned)((~snap) >> 32));
    float bestd = __int_as_float(0x7f800000);
    float bestS = EPSV;
    int bestf = -1;

    for (int t = 0; t < nl; t++) {
        int k = (int)list[t];
        float4 bb = sm[k * 4 + 3];
        if (px < bb.x || px > bb.y || py < bb.z || py > bb.w) continue;
        float zlim = fminf(pruneD, bestd);
        if (sminz[k] * 0.999f > zlim) continue;      // prune-only, huge margin
        float4 q0 = sm[k * 4 + 0];
        float4 q1 = sm[k * 4 + 1];
        // exact eval — champion machinery (reference expressions)
        float e0 = (q1.x - q0.z) * (py - q0.w) - (q1.y - q0.w) * (px - q0.z);
        float e1 = (q0.x - q1.x) * (py - q1.y) - (q0.y - q1.y) * (px - q1.x);
        float b0 = e0 * q1.z;          // sign-exact vs e0/areaS
        float b1 = e1 * q1.z;
        if (b0 >= 0.0f && b1 >= 0.0f) {
            float b2 = 1.0f - b0 - b1;
            bool inside;
            if (b2 > TAU)       inside = true;
            else if (b2 < -TAU) inside = false;
            else {             // boundary band: replicate reference divisions exactly
                float bb0 = e0 / q1.w;
                float bb1 = e1 / q1.w;
                inside = (1.0f - bb0 - bb1) >= 0.0f;
                b0 = bb0; b1 = bb1;
            }
            if (inside) {
                float4 q2 = sm[k * 4 + 2];       // AFTER inside — the law, do not move
                float b2e = 1.0f - b0 - b1;
                float S = b0 * q2.x + b1 * q2.y + b2e * q2.z;
                if (S > bestS) {
                    float d = 1.0f / fmaxf(S, EPSV);     // exact, only on updates
                    if (d < bestd) { bestd = d; bestS = S; bestf = fbeg + k; }
                }
            }
        }
    }

    if (bestf >= 0) {
        unsigned long long key =
            ~(((unsigned long long)__float_as_uint(bestd) << 32) | (unsigned)bestf);
        atomicMax(&g_best[b][pix], key);
    }
}

__global__ void k_shade(const float* __restrict__ verts, const int* __restrict__ faces,
                        float* __restrict__ out) {
    int idx = blockIdx.x * blockDim.x + threadIdx.x;
    if (idx >= NB * IH * IW) return;
    int b = idx / (IH * IW);
    int pix = idx - b * (IH * IW);
    int i = pix / IW, j = pix - i * IW;
    float px = 1.0f - (2.0f * (float)j + 1.0f) * (1.0f / (float)IW);
    float py = 1.0f - (2.0f * (float)i + 1.0f) * (1.0f / (float)IH);

    unsigned long long key = g_best[b][pix];
    g_best[b][pix] = 0ull;                 // self-reset for next replay (own entry only)
    bool hit = (key != 0ull);
    float r = 1.0f, g = 1.0f, bl = 1.0f;
    if (hit) {
        int bestf = (int)((~key) & 0xFFFFFFFFull);
        int i0 = faces[bestf * 3 + 0];
        int i1 = faces[bestf * 3 + 1];
        int i2 = faces[bestf * 3 + 2];
        float a0x = g_vtx[b][i0][0], a0y = g_vtx[b][i0][1], t0 = g_vtx[b][i0][2];
        float a1x = g_vtx[b][i1][0], a1y = g_vtx[b][i1][1], t1 = g_vtx[b][i1][2];
        float a2x = g_vtx[b][i2][0], a2y = g_vtx[b][i2][1], t2 = g_vtx[b][i2][2];
        float ar = (a1x - a0x) * (a2y - a0y) - (a1y - a0y) * (a2x - a0x);
        if (fabsf(ar) < EPSV) ar = EPSV;
        // exact IEEE divisions (champion shade math)
        float bb0 = ((a2x - a1x) * (py - a1y) - (a2y - a1y) * (px - a1x)) / ar;
        float bb1 = ((a0x - a2x) * (py - a2y) - (a0y - a2y) * (px - a2x)) / ar;
        float bb2 = 1.0f - bb0 - bb1;
        float w0 = bb0 / t0, w1 = bb1 / t1, w2 = bb2 / t2;
        float s = w0 + w1 + w2 + EPSV;
        float p0 = w0 / s, p1 = w1 / s, p2 = w2 / s;

        const float* wv0 = &verts[(b * NV + i0) * 3];
        const float* wv1 = &verts[(b * NV + i1) * 3];
        const float* wv2 = &verts[(b * NV + i2) * 3];
        float posx = p0 * wv0[0] + p1 * wv1[0] + p2 * wv2[0];
        float posy = p0 * wv0[1] + p1 * wv1[1] + p2 * wv2[1];
        float posz = p0 * wv0[2] + p1 * wv1[2] + p2 * wv2[2];

        float n0x = g_vn[b][i0][0], n0y = g_vn[b][i0][1], n0z = g_vn[b][i0][2];
        float n1x = g_vn[b][i1][0], n1y = g_vn[b][i1][1], n1z = g_vn[b][i1][2];
        float n2x = g_vn[b][i2][0], n2y = g_vn[b][i2][1], n2z = g_vn[b][i2][2];
        float n0 = sqrtf(n0x * n0x + n0y * n0y + n0z * n0z) + EPSV;
        float n1 = sqrtf(n1x * n1x + n1y * n1y + n1z * n1z) + EPSV;
        float n2 = sqrtf(n2x * n2x + n2y * n2y + n2z * n2z) + EPSV;
        n0x /= n0; n0y /= n0; n0z /= n0;
        n1x /= n1; n1y /= n1; n1z /= n1;
        n2x /= n2; n2y /= n2; n2z /= n2;

        float nx = p0 * n0x + p1 * n1x + p2 * n2x;
        float ny = p0 * n0y + p1 * n1y + p2 * n2y;
        float nz = p0 * n0z + p1 * n1z + p2 * n2z;
        float nn = sqrtf(nx * nx + ny * ny + nz * nz) + EPSV;
        nx /= nn; ny /= nn; nz /= nn;

        float lx = 0.0f - posx, ly = 1.0f - posy, lz = 3.0f - posz;
        float ln = sqrtf(lx * lx + ly * ly + lz * lz) + EPSV;
        lx /= ln; ly /= ln; lz /= ln;
        float vx = 0.0f - posx, vy = 0.0f - posy, vz = 2.0f - posz;
        float vnm = sqrtf(vx * vx + vy * vy + vz * vz) + EPSV;
        vx /= vnm; vy /= vnm; vz /= vnm;

        float dnl = nx * lx + ny * ly + nz * lz;
        float ndl = fmaxf(dnl, 0.0f);
        float rx = 2.0f * dnl * nx - lx;
        float ry = 2.0f * dnl * ny - ly;
        float rz = 2.0f * dnl * nz - lz;
        float sc = fmaxf(rx * vx + ry * vy + rz * vz, 0.0f);
        float s2 = sc * sc, s4 = s2 * s2, s8 = s4 * s4;
        float spec = 0.2f * 0.6f * (s8 * s2);
        float shade = 0.5f + 0.3f * ndl;
        r  = (142.0f / 255.0f) * shade + spec;
        g  = (179.0f / 255.0f) * shade + spec;
        bl = (247.0f / 255.0f) * shade + spec;
    }
    int plane = IH * IW;
    out[(b * 3 + 0) * plane + pix] = r * 255.0f;
    out[(b * 3 + 1) * plane + pix] = g * 255.0f;
    out[(b * 3 + 2) * plane + pix] = bl * 255.0f;
    out[NB * 3 * plane + b * plane + pix] = hit ? 1.0f : 0.0f;
}

extern "C" void kernel_launch(void* const* d_in, const int* in_sizes, int n_in,
                              void* d_out, int out_size) {
    const float* verts = (const float*)d_in[0];
    const int* faces = (const int*)d_in[1];
    float* out = (float*)d_out;

    k_prep<<<(NB * NF + 255) / 256, 256>>>(verts, faces);
    dim3 grid(64, NB, NSPLIT + 1);
    k_render<<<grid, 256>>>(faces);
    k_shade<<<(NB * IH * IW + 255) / 256, 256>>>(verts, faces, out);
}